// round 14
// baseline (speedup 1.0000x reference)
#include <cuda_runtime.h>
#include <cstdint>

#define NT 512
#define NS 64

typedef unsigned long long u64;

// ---------------- packed weight globals -------------------------------------------------
// g_wrzh[c][k2 128][jl 32] = (wr[2k2],wr[2k2+1],wz[2k2],wz[2k2+1]) for j=32c+jl
__device__ float4 g_wrzh[32768];
__device__ float2 g_wnh[32768];    // [c][k2 128][jl 32] n-gate pairs
__device__ float4 g_wrzi[8192];    // [c][k2 32][jl 32]
__device__ float2 g_wni[8192];     // [c][k2 32][jl 32]
__device__ float2 g_wbP[32768];    // [k2 128][j 256]
// h/hb broadcast buffer: [cluster 16][j 256][row 64]
__device__ float g_hbuf[262144];

// ---------------- f32x2 helpers ---------------------------------------------------------
__device__ __forceinline__ u64 pk2(float a, float b) {
    u64 r;
    asm("mov.b64 %0,{%1,%2};" : "=l"(r)
        : "r"(__float_as_uint(a)), "r"(__float_as_uint(b)));
    return r;
}
__device__ __forceinline__ float2 upk2(u64 v) {
    unsigned lo, hi;
    asm("mov.b64 {%0,%1},%2;" : "=r"(lo), "=r"(hi) : "l"(v));
    return make_float2(__uint_as_float(lo), __uint_as_float(hi));
}
__device__ __forceinline__ void ffma2(u64& d, u64 a, u64 b) {
    asm("fma.rn.f32x2 %0,%1,%2,%3;" : "=l"(d) : "l"(a), "l"(b), "l"(d));
}
__device__ __forceinline__ float hsum2(u64 v) {
    float2 f = upk2(v);
    return f.x + f.y;
}
__device__ __forceinline__ float sigmoidf_(float x) { return 1.f / (1.f + __expf(-x)); }
__device__ __forceinline__ float tanhf_(float x) { return 1.f - 2.f / (__expf(2.f * x) + 1.f); }

// ---------------- prep: pack per-CTA weight slices --------------------------------------
__global__ void __launch_bounds__(256) prep_kernel(const float* __restrict__ w_ih,
                                                   const float* __restrict__ w_hh,
                                                   const float* __restrict__ w_base) {
    int idx = blockIdx.x * 256 + threadIdx.x;
    if (idx < 32768) {  // g_wrzh: [c 8][k2 128][jl 32]
        int c = idx >> 12, k2 = (idx >> 5) & 127, jl = idx & 31;
        int j = 32 * c + jl;
        const float* wr = w_hh + (size_t)j * 256;
        const float* wz = w_hh + (size_t)(256 + j) * 256;
        g_wrzh[idx] = make_float4(wr[2 * k2], wr[2 * k2 + 1], wz[2 * k2], wz[2 * k2 + 1]);
        return;
    }
    idx -= 32768;
    if (idx < 32768) {  // g_wnh
        int c = idx >> 12, k2 = (idx >> 5) & 127, jl = idx & 31;
        int j = 32 * c + jl;
        const float* wn = w_hh + (size_t)(512 + j) * 256;
        g_wnh[idx] = make_float2(wn[2 * k2], wn[2 * k2 + 1]);
        return;
    }
    idx -= 32768;
    if (idx < 8192) {  // g_wrzi: [c 8][k2 32][jl 32]
        int c = idx >> 10, k2 = (idx >> 5) & 31, jl = idx & 31;
        int j = 32 * c + jl;
        const float* wr = w_ih + (size_t)j * 64;
        const float* wz = w_ih + (size_t)(256 + j) * 64;
        g_wrzi[idx] = make_float4(wr[2 * k2], wr[2 * k2 + 1], wz[2 * k2], wz[2 * k2 + 1]);
        return;
    }
    idx -= 8192;
    if (idx < 8192) {  // g_wni
        int c = idx >> 10, k2 = (idx >> 5) & 31, jl = idx & 31;
        int j = 32 * c + jl;
        const float* wn = w_ih + (size_t)(512 + j) * 64;
        g_wni[idx] = make_float2(wn[2 * k2], wn[2 * k2 + 1]);
        return;
    }
    idx -= 8192;
    if (idx < 32768) {  // g_wbP [k2][j]
        int k2 = idx >> 8, j = idx & 255;
        const float* row = w_base + (size_t)j * 256;
        g_wbP[idx] = make_float2(row[2 * k2], row[2 * k2 + 1]);
    }
}

// ---------------- SMEM layout (221184 bytes) --------------------------------------------
#define OFF_WRZH 0        // [128 k2][32 jl] float4 = 64 KB (resident)
#define OFF_WNH 65536     // [128][32] float2 = 32 KB
#define OFF_WRZI 98304    // [32][32] float4 = 16 KB
#define OFF_WNI 114688    // [32][32] float2 = 8 KB
#define OFF_HS 122880     // [128 k2][32 rp] ulonglong2 = 64 KB
#define OFF_XS 188416     // [32 k2][32 rp] ulonglong2 = 16 KB  (overlaid by exch)
#define OFF_EXCH 188416   // [64 row][32 jl] float4 = 32 KB (overlays xs + 16 KB more)
#define SMEM_TOTAL 221184

#define CLUSTER_BARRIER()                                              \
    do {                                                               \
        asm volatile("barrier.cluster.arrive.aligned;" ::: "memory"); \
        asm volatile("barrier.cluster.wait.aligned;" ::: "memory");   \
    } while (0)

// ---------------- main: 16 clusters x 8 CTAs; CTA owns 32 h-dims, cluster owns 64 rows --
__global__ void __launch_bounds__(512, 1) __cluster_dims__(8, 1, 1) actor_kernel(
    const float* __restrict__ x, const float* __restrict__ b_ih,
    const float* __restrict__ b_hh, const float* __restrict__ b_base,
    const float* __restrict__ w_dir, const float* __restrict__ b_dir,
    const float* __restrict__ w_mag, const float* __restrict__ b_mag,
    float* __restrict__ out) {
    extern __shared__ char smem[];
    ulonglong2* hs = (ulonglong2*)(smem + OFF_HS);
    ulonglong2* xs = (ulonglong2*)(smem + OFF_XS);
    float4* exch = (float4*)(smem + OFF_EXCH);
    float* exchF = (float*)(smem + OFF_EXCH);

    const int tid = threadIdx.x;
    const int jl = tid & 31;          // local gate dim
    const int kh = (tid >> 5) & 1;    // k-half
    const int rpg = tid >> 6;         // row-pair group [0,8)
    const int c = blockIdx.x & 7;     // cluster rank
    const int g = blockIdx.x >> 3;    // cluster id
    const int j = 32 * c + jl;        // global gate dim owned

    // ---- load resident weight slices (once) ----
    {
        float4* wrzh = (float4*)(smem + OFF_WRZH);
        float2* wnh = (float2*)(smem + OFF_WNH);
        float4* wrzi = (float4*)(smem + OFF_WRZI);
        float2* wni = (float2*)(smem + OFF_WNI);
        const float4* s1 = g_wrzh + c * 4096;
        const float2* s2 = g_wnh + c * 4096;
        const float4* s3 = g_wrzi + c * 1024;
        const float2* s4 = g_wni + c * 1024;
#pragma unroll
        for (int q = 0; q < 8; ++q) wrzh[tid + q * 512] = s1[tid + q * 512];
#pragma unroll
        for (int q = 0; q < 8; ++q) wnh[tid + q * 512] = s2[tid + q * 512];
#pragma unroll
        for (int q = 0; q < 2; ++q) wrzi[tid + q * 512] = s3[tid + q * 512];
#pragma unroll
        for (int q = 0; q < 2; ++q) wni[tid + q * 512] = s4[tid + q * 512];
        // zero h state
#pragma unroll
        for (int q = 0; q < 8; ++q) hs[tid + q * 512] = make_ulonglong2(0ULL, 0ULL);
    }

    const float br = b_ih[j] + b_hh[j];
    const float bz = b_ih[256 + j] + b_hh[256 + j];
    const float bi = b_ih[512 + j];
    const float bh = b_hh[512 + j];

    float hreg[8];
#pragma unroll
    for (int i = 0; i < 8; i++) hreg[i] = 0.f;

    // ---- x staging: 2 quads/thread; quad idx -> (k2 = idx>>5, rp = idx&31) ----
    const int xk2_0 = tid >> 5, xrp_0 = tid & 31;          // quad 0 (idx = tid, k2 in [0,16))
    const int xk2_1 = (tid + 512) >> 5, xrp_1 = tid & 31;  // quad 1 (k2 in [16,32))
    const float* xq0 = x + (size_t)(64 * g + 2 * xrp_0) * NT * NS + 2 * xk2_0;
    const float* xq1 = x + (size_t)(64 * g + 2 * xrp_1) * NT * NS + 2 * xk2_1;
    float2 xa0, xb0, xa1, xb1;
    // load t=0
    xa0 = *(const float2*)xq0;
    xb0 = *(const float2*)(xq0 + NT * NS);
    xa1 = *(const float2*)xq1;
    xb1 = *(const float2*)(xq1 + NT * NS);
    xs[xk2_0 * 32 + xrp_0] = make_ulonglong2(pk2(xa0.x, xa0.y), pk2(xb0.x, xb0.y));
    xs[xk2_1 * 32 + xrp_1] = make_ulonglong2(pk2(xa1.x, xa1.y), pk2(xb1.x, xb1.y));
    __syncthreads();  // weights, hs, xs(0) ready

    const ulonglong2* wrzp = (const ulonglong2*)(smem + OFF_WRZH) + (size_t)(kh * 64) * 32 + jl;
    const u64* wnp = (const u64*)(smem + OFF_WNH) + (size_t)(kh * 64) * 32 + jl;
    const ulonglong2* wrzip = (const ulonglong2*)(smem + OFF_WRZI) + (size_t)(kh * 16) * 32 + jl;
    const u64* wnip = (const u64*)(smem + OFF_WNI) + (size_t)(kh * 16) * 32 + jl;
    const ulonglong2* hsp = hs + (size_t)(kh * 64) * 32 + rpg;
    const ulonglong2* xsp = xs + (size_t)(kh * 16) * 32 + rpg;
    const int hoff = (g * 256 + j) * 64;

    for (int t = 0; t < NT; ++t) {
        // prefetch x(t+1) into regs
        if (t + 1 < NT) {
            const float* p0 = xq0 + (size_t)(t + 1) * NS;
            const float* p1 = xq1 + (size_t)(t + 1) * NS;
            xa0 = *(const float2*)p0;
            xb0 = *(const float2*)(p0 + NT * NS);
            xa1 = *(const float2*)p1;
            xb1 = *(const float2*)(p1 + NT * NS);
        }

        u64 aR[8], aZ[8], aNi[8], aNh[8];
#pragma unroll
        for (int b = 0; b < 8; b++) { aR[b] = aZ[b] = aNi[b] = aNh[b] = 0ULL; }

        // ---- input part: 16 k2 ----
#pragma unroll 4
        for (int k2 = 0; k2 < 16; ++k2) {
            ulonglong2 wv = wrzip[k2 * 32];
            u64 wn = wnip[k2 * 32];
            const ulonglong2* hq = xsp + k2 * 32;
#pragma unroll
            for (int m = 0; m < 4; ++m) {
                ulonglong2 hv = hq[8 * m];
                ffma2(aR[2 * m], wv.x, hv.x);
                ffma2(aR[2 * m + 1], wv.x, hv.y);
                ffma2(aZ[2 * m], wv.y, hv.x);
                ffma2(aZ[2 * m + 1], wv.y, hv.y);
                ffma2(aNi[2 * m], wn, hv.x);
                ffma2(aNi[2 * m + 1], wn, hv.y);
            }
        }
        // ---- recurrent part: 64 k2 ----
#pragma unroll 4
        for (int k2 = 0; k2 < 64; ++k2) {
            ulonglong2 wv = wrzp[k2 * 32];
            u64 wn = wnp[k2 * 32];
            const ulonglong2* hq = hsp + k2 * 32;
#pragma unroll
            for (int m = 0; m < 4; ++m) {
                ulonglong2 hv = hq[8 * m];
                ffma2(aR[2 * m], wv.x, hv.x);
                ffma2(aR[2 * m + 1], wv.x, hv.y);
                ffma2(aZ[2 * m], wv.y, hv.x);
                ffma2(aZ[2 * m + 1], wv.y, hv.y);
                ffma2(aNh[2 * m], wn, hv.x);
                ffma2(aNh[2 * m + 1], wn, hv.y);
            }
        }

        __syncthreads();  // all xs/hs reads done (exch overlays xs)

        if (kh) {
#pragma unroll
            for (int m = 0; m < 4; ++m) {
#pragma unroll
                for (int s = 0; s < 2; ++s) {
                    int r8 = 2 * m + s;
                    int row = 2 * (rpg + 8 * m) + s;
                    exch[row * 32 + jl] = make_float4(hsum2(aR[r8]), hsum2(aZ[r8]),
                                                      hsum2(aNi[r8]), hsum2(aNh[r8]));
                }
            }
        }
        __syncthreads();  // exch ready

        if (!kh) {
#pragma unroll
            for (int m = 0; m < 4; ++m) {
#pragma unroll
                for (int s = 0; s < 2; ++s) {
                    int r8 = 2 * m + s;
                    int row = 2 * (rpg + 8 * m) + s;
                    float4 p = exch[row * 32 + jl];
                    float r = sigmoidf_(hsum2(aR[r8]) + p.x + br);
                    float z = sigmoidf_(hsum2(aZ[r8]) + p.y + bz);
                    float n = tanhf_(hsum2(aNi[r8]) + p.z + bi +
                                     r * (hsum2(aNh[r8]) + p.w + bh));
                    hreg[r8] = (1.f - z) * n + z * hreg[r8];
                }
                *(float2*)&g_hbuf[hoff + 2 * (rpg + 8 * m)] =
                    make_float2(hreg[2 * m], hreg[2 * m + 1]);
            }
        }
        __threadfence();
        CLUSTER_BARRIER();  // all CTAs' h slabs visible in L2

        // rebuild full hs from g_hbuf: 8 quads/thread
#pragma unroll
        for (int q = 0; q < 8; ++q) {
            int idx = tid + q * 512;
            int k2 = idx >> 5, rp = idx & 31;
            const float* hb0 = &g_hbuf[(g * 256 + 2 * k2) * 64 + 2 * rp];
            float2 a = *(const float2*)hb0;         // rows 2rp,2rp+1 @ dim 2k2
            float2 b = *(const float2*)(hb0 + 64);  // @ dim 2k2+1
            hs[idx] = make_ulonglong2(pk2(a.x, b.x), pk2(a.y, b.y));
        }
        // stage x(t+1)
        if (t + 1 < NT) {
            xs[xk2_0 * 32 + xrp_0] = make_ulonglong2(pk2(xa0.x, xa0.y), pk2(xb0.x, xb0.y));
            xs[xk2_1 * 32 + xrp_1] = make_ulonglong2(pk2(xa1.x, xa1.y), pk2(xb1.x, xb1.y));
        }
        __syncthreads();  // hs(t+1), xs(t+1) ready
    }

    // ---------------- base layer: hb[row][j] = relu(h[row] . w_base[j] + b_base[j]) -----
    {
        u64 aB[8];
#pragma unroll
        for (int b = 0; b < 8; b++) aB[b] = 0ULL;
        const u64* wbp = (const u64*)g_wbP + (size_t)(kh * 64) * 256 + j;
#pragma unroll 4
        for (int k2 = 0; k2 < 64; ++k2) {
            u64 wb = wbp[k2 * 256];
            const ulonglong2* hq = hsp + k2 * 32;
#pragma unroll
            for (int m = 0; m < 4; ++m) {
                ulonglong2 hv = hq[8 * m];
                ffma2(aB[2 * m], wb, hv.x);
                ffma2(aB[2 * m + 1], wb, hv.y);
            }
        }
        __syncthreads();  // hs reads done (exchF overlays xs region only, but be safe)
        if (kh) {
#pragma unroll
            for (int m = 0; m < 4; ++m)
#pragma unroll
                for (int s = 0; s < 2; ++s)
                    exchF[(2 * (rpg + 8 * m) + s) * 32 + jl] = hsum2(aB[2 * m + s]);
        }
        __syncthreads();
        if (!kh) {
            float bb = b_base[j];
#pragma unroll
            for (int m = 0; m < 4; ++m) {
                float v0 = fmaxf(hsum2(aB[2 * m]) + exchF[(2 * (rpg + 8 * m)) * 32 + jl] + bb, 0.f);
                float v1 = fmaxf(hsum2(aB[2 * m + 1]) + exchF[(2 * (rpg + 8 * m) + 1) * 32 + jl] + bb, 0.f);
                *(float2*)&g_hbuf[hoff + 2 * (rpg + 8 * m)] = make_float2(v0, v1);
            }
        }
        __threadfence();
        CLUSTER_BARRIER();
    }

    // ---------------- heads: CTA handles cluster-local rows [8c, 8c+8) ------------------
    // stage hb rows into SMEM: 8 rows x 256 dims
    __syncthreads();
    for (int idx = tid; idx < 2048; idx += 512) {
        int i = idx >> 8, kd = idx & 255;
        exchF[idx] = g_hbuf[(g * 256 + kd) * 64 + 8 * c + i];
    }
    __syncthreads();
    if (tid < 64) {
        int b = tid >> 3, a = tid & 7;
        float aD = b_dir[a], aM = b_mag[a];
        const float* __restrict__ wd = w_dir + a * 256;
        const float* __restrict__ wm = w_mag + a * 256;
#pragma unroll 4
        for (int k = 0; k < 256; ++k) {
            float hv = exchF[b * 256 + k];
            aD = fmaf(wd[k], hv, aD);
            aM = fmaf(wm[k], hv, aM);
        }
        out[(size_t)(64 * g + 8 * c + b) * 8 + a] = tanhf_(aD) * sigmoidf_(aM);
    }
}

// ---------------- launch ----------------------------------------------------------------
extern "C" void kernel_launch(void* const* d_in, const int* in_sizes, int n_in,
                              void* d_out, int out_size) {
    const float* x      = (const float*)d_in[0];
    const float* w_ih   = (const float*)d_in[1];
    const float* w_hh   = (const float*)d_in[2];
    const float* b_ih   = (const float*)d_in[3];
    const float* b_hh   = (const float*)d_in[4];
    const float* w_base = (const float*)d_in[5];
    const float* b_base = (const float*)d_in[6];
    const float* w_dir  = (const float*)d_in[7];
    const float* b_dir  = (const float*)d_in[8];
    const float* w_mag  = (const float*)d_in[9];
    const float* b_mag  = (const float*)d_in[10];

    static int configured = 0;
    if (!configured) {
        cudaFuncSetAttribute(actor_kernel, cudaFuncAttributeMaxDynamicSharedMemorySize,
                             SMEM_TOTAL);
        configured = 1;
    }

    // 32768*2 + 8192*2 + 32768 = 114688 elements -> 448 blocks of 256
    prep_kernel<<<448, 256>>>(w_ih, w_hh, w_base);
    actor_kernel<<<128, 512, SMEM_TOTAL>>>(x, b_ih, b_hh, b_base, w_dir, b_dir, w_mag,
                                           b_mag, (float*)d_out);
}

// round 16
// speedup vs baseline: 3.4666x; 3.4666x over previous
#include <cuda_runtime.h>
#include <cstdint>

#define NT 512
#define NS 64

typedef unsigned long long u64;

// ---------------- packed weights, k2-interleaved by gate (R9 layout, tail-padded) -------
// g_whRZ[k2*256+j] = (w_hh_r[j][2k2], w_hh_r[j][2k2+1], w_hh_z[j][2k2], w_hh_z[j][2k2+1])
// g_whN [k2*256+j] = (w_hh_n[j][2k2], w_hh_n[j][2k2+1])
// padded to 132 k2 rows so the software pipeline may prefetch 2-3 k2 past the end
__device__ float4 g_whRZ[132 * 256];
__device__ float2 g_whN[132 * 256];
__device__ float4 g_wiRZ[36 * 256];
__device__ float2 g_wiN[36 * 256];
__device__ float2 g_wbP[132 * 256];

// ---------------- f32x2 helpers ---------------------------------------------------------
__device__ __forceinline__ u64 pk2(float a, float b) {
    u64 r;
    asm("mov.b64 %0,{%1,%2};" : "=l"(r)
        : "r"(__float_as_uint(a)), "r"(__float_as_uint(b)));
    return r;
}
__device__ __forceinline__ float2 upk2(u64 v) {
    unsigned lo, hi;
    asm("mov.b64 {%0,%1},%2;" : "=r"(lo), "=r"(hi) : "l"(v));
    return make_float2(__uint_as_float(lo), __uint_as_float(hi));
}
__device__ __forceinline__ void ffma2(u64& d, u64 a, u64 b) {
    asm("fma.rn.f32x2 %0,%1,%2,%3;" : "=l"(d) : "l"(a), "l"(b), "l"(d));
}
__device__ __forceinline__ float hsum2(u64 v) {
    float2 f = upk2(v);
    return f.x + f.y;
}
__device__ __forceinline__ float sigmoidf_(float x) { return 1.f / (1.f + __expf(-x)); }
__device__ __forceinline__ float tanhf_(float x) { return 1.f - 2.f / (__expf(2.f * x) + 1.f); }

// ---------------- prep: transpose + pack (R9-identical indexing) ------------------------
__global__ void __launch_bounds__(256) prep_kernel(const float* __restrict__ w_ih,
                                                   const float* __restrict__ w_hh,
                                                   const float* __restrict__ w_base) {
    int idx = blockIdx.x * 256 + threadIdx.x;
    if (idx < 32768) {  // g_whRZ
        int k2 = idx >> 8, j = idx & 255;
        const float* wr = w_hh + (size_t)j * 256;
        const float* wz = w_hh + (size_t)(256 + j) * 256;
        g_whRZ[idx] = make_float4(wr[2 * k2], wr[2 * k2 + 1], wz[2 * k2], wz[2 * k2 + 1]);
        return;
    }
    idx -= 32768;
    if (idx < 32768) {  // g_whN
        int k2 = idx >> 8, j = idx & 255;
        const float* wn = w_hh + (size_t)(512 + j) * 256;
        g_whN[idx] = make_float2(wn[2 * k2], wn[2 * k2 + 1]);
        return;
    }
    idx -= 32768;
    if (idx < 8192) {  // g_wiRZ
        int k2 = idx >> 8, j = idx & 255;
        const float* wr = w_ih + (size_t)j * 64;
        const float* wz = w_ih + (size_t)(256 + j) * 64;
        g_wiRZ[idx] = make_float4(wr[2 * k2], wr[2 * k2 + 1], wz[2 * k2], wz[2 * k2 + 1]);
        return;
    }
    idx -= 8192;
    if (idx < 8192) {  // g_wiN
        int k2 = idx >> 8, j = idx & 255;
        const float* wn = w_ih + (size_t)(512 + j) * 64;
        g_wiN[idx] = make_float2(wn[2 * k2], wn[2 * k2 + 1]);
        return;
    }
    idx -= 8192;
    if (idx < 32768) {  // g_wbP
        int k2 = idx >> 8, j = idx & 255;
        const float* row = w_base + (size_t)j * 256;
        g_wbP[idx] = make_float2(row[2 * k2], row[2 * k2 + 1]);
    }
}

// ---------------- main: 128 CTAs x 512 threads; 8 rows/CTA; thread = (j, k-half) --------
// hs[k2][bp] floats: [h[2bp][2k2], h[2bp][2k2+1], h[2bp+1][2k2], h[2bp+1][2k2+1]]
__global__ void __launch_bounds__(512, 1) actor_kernel(
    const float* __restrict__ x, const float* __restrict__ b_ih,
    const float* __restrict__ b_hh, const float* __restrict__ b_base,
    const float* __restrict__ w_dir, const float* __restrict__ b_dir,
    const float* __restrict__ w_mag, const float* __restrict__ b_mag,
    float* __restrict__ out) {
    __shared__ ulonglong2 hs[128][4];     // 8 KB
    __shared__ ulonglong2 xs[2][32][4];   // 4 KB
    __shared__ float4 exch[8][256];       // 32 KB

    const int tid = threadIdx.x;
    const int j = tid & 255;   // gate dim
    const int kh = tid >> 8;   // k-half
    const int bbase = blockIdx.x * 8;

    ((ulonglong2*)hs)[tid] = make_ulonglong2(0ULL, 0ULL);

    const float br = b_ih[j] + b_hh[j];
    const float bz = b_ih[256 + j] + b_hh[256 + j];
    const float bi = b_ih[512 + j];
    const float bh = b_hh[512 + j];

    float hreg[8];
#pragma unroll
    for (int i = 0; i < 8; i++) hreg[i] = 0.f;

    // x prefetch: threads 0..127 each own (row, 4-float chunk)
    const int xrow = tid >> 4, xc = tid & 15;
    const float* xptr = x + (size_t)(bbase + xrow) * NT * NS + xc * 4;
    float4 xr = make_float4(0.f, 0.f, 0.f, 0.f);
    if (tid < 128) xr = *(const float4*)xptr;

    // single-base weight pointers; inner offsets are k2*const immediates
    const ulonglong2* __restrict__ pRZ =
        (const ulonglong2*)g_whRZ + (size_t)kh * 64 * 256 + j;
    const u64* __restrict__ pN = (const u64*)g_whN + (size_t)kh * 64 * 256 + j;
    const ulonglong2* __restrict__ piRZ =
        (const ulonglong2*)g_wiRZ + (size_t)kh * 16 * 256 + j;
    const u64* __restrict__ piN = (const u64*)g_wiN + (size_t)kh * 16 * 256 + j;
    const ulonglong2* hbase = &hs[kh * 64][0];

    for (int t = 0; t < NT; ++t) {
        const int buf = t & 1;
        if (tid < 128) {
            ((u64*)&xs[buf][2 * xc][xrow >> 1])[xrow & 1] = pk2(xr.x, xr.y);
            ((u64*)&xs[buf][2 * xc + 1][xrow >> 1])[xrow & 1] = pk2(xr.z, xr.w);
            if (t + 1 < NT) xr = *(const float4*)(xptr + (size_t)(t + 1) * NS);
        }
        __syncthreads();  // x_t staged; h(t-1) visible; exch free

        u64 aR[8], aZ[8], aNi[8], aNh[8];
#pragma unroll
        for (int b = 0; b < 8; b++) { aR[b] = aZ[b] = aNi[b] = aNh[b] = 0ULL; }

        // ---- input part: 16 k-pairs (short; plain unroll) ----
        const ulonglong2* xbase = &xs[buf][kh * 16][0];
#pragma unroll 4
        for (int k2 = 0; k2 < 16; ++k2) {
            ulonglong2 wrz = piRZ[k2 * 256];
            u64 wn = piN[k2 * 256];
#pragma unroll
            for (int bp = 0; bp < 4; ++bp) {
                ulonglong2 hv = xbase[k2 * 4 + bp];
                ffma2(aR[2 * bp], wrz.x, hv.x);
                ffma2(aR[2 * bp + 1], wrz.x, hv.y);
                ffma2(aZ[2 * bp], wrz.y, hv.x);
                ffma2(aZ[2 * bp + 1], wrz.y, hv.y);
                ffma2(aNi[2 * bp], wn, hv.x);
                ffma2(aNi[2 * bp + 1], wn, hv.y);
            }
        }

        // ---- recurrent part: 64 k-pairs, explicit 2-deep register pipeline ----
        {
            ulonglong2 wA = pRZ[0];
            u64 nA = pN[0];
            ulonglong2 wB = pRZ[256];
            u64 nB = pN[256];
#pragma unroll 2
            for (int k2 = 0; k2 < 64; k2 += 2) {
                // prefetch k2+2, k2+3 (tail-padded arrays make OOB reads harmless)
                ulonglong2 wC = pRZ[(k2 + 2) * 256];
                u64 nC = pN[(k2 + 2) * 256];
                ulonglong2 wD = pRZ[(k2 + 3) * 256];
                u64 nD = pN[(k2 + 3) * 256];
                // compute k2 with (wA, nA)
#pragma unroll
                for (int bp = 0; bp < 4; ++bp) {
                    ulonglong2 hv = hbase[k2 * 4 + bp];
                    ffma2(aR[2 * bp], wA.x, hv.x);
                    ffma2(aR[2 * bp + 1], wA.x, hv.y);
                    ffma2(aZ[2 * bp], wA.y, hv.x);
                    ffma2(aZ[2 * bp + 1], wA.y, hv.y);
                    ffma2(aNh[2 * bp], nA, hv.x);
                    ffma2(aNh[2 * bp + 1], nA, hv.y);
                }
                // compute k2+1 with (wB, nB)
#pragma unroll
                for (int bp = 0; bp < 4; ++bp) {
                    ulonglong2 hv = hbase[(k2 + 1) * 4 + bp];
                    ffma2(aR[2 * bp], wB.x, hv.x);
                    ffma2(aR[2 * bp + 1], wB.x, hv.y);
                    ffma2(aZ[2 * bp], wB.y, hv.x);
                    ffma2(aZ[2 * bp + 1], wB.y, hv.y);
                    ffma2(aNh[2 * bp], nB, hv.x);
                    ffma2(aNh[2 * bp + 1], nB, hv.y);
                }
                wA = wC; nA = nC; wB = wD; nB = nD;
            }
        }

        // kh=1 publishes horizontally-reduced partials
        if (kh) {
#pragma unroll
            for (int b = 0; b < 8; ++b)
                exch[b][j] = make_float4(hsum2(aR[b]), hsum2(aZ[b]),
                                         hsum2(aNi[b]), hsum2(aNh[b]));
        }
        __syncthreads();  // exch ready; all hs reads done

        // kh=0 combines, gate math, writes new h
        if (!kh) {
            const int k2w = j >> 1, par = j & 1;
#pragma unroll
            for (int b = 0; b < 8; ++b) {
                float4 p = exch[b][j];
                float r = sigmoidf_(hsum2(aR[b]) + p.x + br);
                float z = sigmoidf_(hsum2(aZ[b]) + p.y + bz);
                float n = tanhf_(hsum2(aNi[b]) + p.z + bi +
                                 r * (hsum2(aNh[b]) + p.w + bh));
                hreg[b] = (1.f - z) * n + z * hreg[b];
                ((float*)&hs[k2w][b >> 1])[(b & 1) * 2 + par] = hreg[b];
            }
        }
    }
    __syncthreads();  // final h visible

    // base layer (k-split): hb[b][j] = relu(h[b] . w_base[j] + b_base[j])
    {
        u64 aB[8];
#pragma unroll
        for (int b = 0; b < 8; b++) aB[b] = 0ULL;
        const u64* __restrict__ pWb = (const u64*)g_wbP + (size_t)kh * 64 * 256 + j;
#pragma unroll 4
        for (int k2 = 0; k2 < 64; ++k2) {
            u64 wb = pWb[k2 * 256];
#pragma unroll
            for (int bp = 0; bp < 4; ++bp) {
                ulonglong2 hv = hbase[k2 * 4 + bp];
                ffma2(aB[2 * bp], wb, hv.x);
                ffma2(aB[2 * bp + 1], wb, hv.y);
            }
        }
        float* exf = (float*)exch;
        if (kh) {
#pragma unroll
            for (int b = 0; b < 8; ++b) exf[b * 256 + j] = hsum2(aB[b]);
        }
        __syncthreads();
        if (!kh) {
            float bb = b_base[j];
#pragma unroll
            for (int b = 0; b < 8; ++b)
                exf[b * 256 + j] = fmaxf(hsum2(aB[b]) + exf[b * 256 + j] + bb, 0.f);
        }
        __syncthreads();
    }

    // factorized heads: 64 outputs per CTA
    if (tid < 64) {
        const float* hb = (const float*)exch;
        int b = tid >> 3, a = tid & 7;
        float aD = b_dir[a], aM = b_mag[a];
        const float* __restrict__ wd = w_dir + a * 256;
        const float* __restrict__ wm = w_mag + a * 256;
#pragma unroll 4
        for (int k = 0; k < 256; ++k) {
            float hv = hb[b * 256 + k];
            aD = fmaf(wd[k], hv, aD);
            aM = fmaf(wm[k], hv, aM);
        }
        out[(size_t)(bbase + b) * 8 + a] = tanhf_(aD) * sigmoidf_(aM);
    }
}

// ---------------- launch ----------------------------------------------------------------
extern "C" void kernel_launch(void* const* d_in, const int* in_sizes, int n_in,
                              void* d_out, int out_size) {
    const float* x      = (const float*)d_in[0];
    const float* w_ih   = (const float*)d_in[1];
    const float* w_hh   = (const float*)d_in[2];
    const float* b_ih   = (const float*)d_in[3];
    const float* b_hh   = (const float*)d_in[4];
    const float* w_base = (const float*)d_in[5];
    const float* b_base = (const float*)d_in[6];
    const float* w_dir  = (const float*)d_in[7];
    const float* b_dir  = (const float*)d_in[8];
    const float* w_mag  = (const float*)d_in[9];
    const float* b_mag  = (const float*)d_in[10];

    prep_kernel<<<448, 256>>>(w_ih, w_hh, w_base);
    actor_kernel<<<128, 512>>>(x, b_ih, b_hh, b_base, w_dir, b_dir, w_mag, b_mag,
                               (float*)d_out);
}